// round 7
// baseline (speedup 1.0000x reference)
#include <cuda_runtime.h>
#include <stdint.h>
#include <math.h>

#define NQ   12
#define NL   6
#define NC   64
#define TPB  256
#define ST4  17                    // float4 stride per row (odd -> conflict-free phases)
#define NROW 256
#define SMEM4 (NROW * ST4)         // 4352 float4 = 69632 B

typedef unsigned long long u64;
#define SGN2 0x8000000080000000ULL

// Two batch samples per block, packed in f32x2 lanes (lo = sample0, hi = sample1).
// Amp index i[11:0], wire w = bit 11-w.
// M0: row = i[11:4], k = i[3:0]   (local wires 8-11; k-bit masks 8,4,2,1)
// M1: row = (i[11:8]<<4)|i[3:0], k = i[7:4]   (local wires 4-7)
// M2: row = (i[7:4]<<4)|i[3:0] = i&255, k = i[11:8]  (local wires 0-3)

extern __shared__ float4 sm4[];

__device__ __forceinline__ u64 bc2(float c){ u64 r; asm("mov.b64 %0, {%1, %1};" : "=l"(r) : "f"(c)); return r; }
__device__ __forceinline__ u64 pk2(float lo, float hi){ u64 r; asm("mov.b64 %0, {%1, %2};" : "=l"(r) : "f"(lo), "f"(hi)); return r; }
__device__ __forceinline__ float lo32(u64 v){ float f; asm("{ .reg .f32 h; mov.b64 {%0, h}, %1; }" : "=f"(f) : "l"(v)); return f; }
__device__ __forceinline__ float hi32(u64 v){ float f; asm("{ .reg .f32 l; mov.b64 {l, %0}, %1; }" : "=f"(f) : "l"(v)); return f; }
__device__ __forceinline__ u64 mul2(u64 a, u64 b){ u64 r; asm("mul.rn.f32x2 %0, %1, %2;" : "=l"(r) : "l"(a), "l"(b)); return r; }
__device__ __forceinline__ u64 fma2(u64 a, u64 b, u64 c){ u64 r; asm("fma.rn.f32x2 %0, %1, %2, %3;" : "=l"(r) : "l"(a), "l"(b), "l"(c)); return r; }
__device__ __forceinline__ u64 add2(u64 a, u64 b){ u64 r; asm("add.rn.f32x2 %0, %1, %2;" : "=l"(r) : "l"(a), "l"(b)); return r; }
__device__ __forceinline__ u64 rxh(u64 C2, u64 S2, u64 T, u64 U){ return fma2(C2, T, mul2(S2, U)); }

// RX on one register-local wire (k-bit mask mp) over 16 packed amps (2 samples/lane)
__device__ __forceinline__ void rx_gate(u64* R, u64* I, float c, float s, int mp)
{
    const u64 C2 = bc2(c), S2 = bc2(s), N2 = S2 ^ SGN2;
#pragma unroll
    for (int p0 = 0; p0 < 16; ++p0) {
        if (p0 & mp) continue;
        const int p1 = p0 | mp;
        const u64 r0 = R[p0], i0 = I[p0], r1 = R[p1], i1 = I[p1];
        R[p0] = rxh(C2, S2, r0, i1);
        I[p0] = rxh(C2, N2, i0, r1);
        R[p1] = rxh(C2, S2, r1, i0);
        I[p1] = rxh(C2, N2, i1, r0);
    }
}

__global__ __launch_bounds__(TPB, 2)
void qnn_kernel(const float* __restrict__ x,
                const float* __restrict__ qw,
                const float* __restrict__ W,
                const float* __restrict__ bias,
                float* __restrict__ out)
{
    __shared__ u64  cxu[NQ], sxu[NQ];      // per-sample-pair embedding angles
    __shared__ float cq[NL * NQ], sq[NL * NQ];
    __shared__ u64  redu[8][NQ];
    __shared__ u64  zfu[NQ];

    const int tid = threadIdx.x;
    const int b0  = blockIdx.x * 2;        // samples b0, b0+1
    const int lane = tid & 31;
    const int warp = tid >> 5;

    if (tid < NQ) {
        float s0, c0, s1, c1;
        sincosf(0.5f * x[b0 * NQ + tid], &s0, &c0);
        sincosf(0.5f * x[(b0 + 1) * NQ + tid], &s1, &c1);
        cxu[tid] = pk2(c0, c1); sxu[tid] = pk2(s0, s1);
    }
    if (tid >= 32 && tid < 32 + NL * NQ) {
        const int idx = tid - 32;
        float s, c;
        sincosf(0.5f * qw[idx], &s, &c);
        cq[idx] = c; sq[idx] = s;
    }
    __syncthreads();

    // ---- init (M0): fused AngleEmbedding product state, 2 samples packed ----
    u64 R[16], I[16];
    uint32_t off3p[8];                     // 16 T3 gather offsets (2x u16)
    const int base = tid << 4;

#pragma unroll
    for (int k = 0; k < 16; ++k) {
        const int i = base | k;
        u64 m = ((i >> 11) & 1) ? sxu[0] : cxu[0];
#pragma unroll
        for (int w = 1; w < NQ; ++w)
            m = mul2(m, ((i >> (11 - w)) & 1) ? sxu[w] : cxu[w]);
        const int pc = __popc(i) & 3;      // amp = mag * (-i)^popcount
        const u64 z = 0ull, nm = m ^ SGN2;
        R[k] = (pc == 0) ? m : (pc == 2) ? nm : z;
        I[k] = (pc == 1) ? nm : (pc == 3) ? m : z;

        // sigma(i): CNOT-ring gather source j (new[i] = old[j]); address under M2
        int j = i;
#pragma unroll
        for (int w = NQ - 1; w >= 0; --w) {
            const int t  = (w + 1) % NQ;
            const int bc = (j >> (11 - w)) & 1;
            j ^= bc << (11 - t);
        }
        const uint32_t off = (uint32_t)((j & 255) * ST4 + (j >> 8));
        if (k & 1) off3p[k >> 1] |= off << 16;
        else       off3p[k >> 1]  = off;
    }

    const int st    = tid * ST4;                                 // store base (all rounds)
    const int base1 = (tid & 0xF0) * ST4 + (tid & 15);           // T1: + k*ST4
    const int base2 = (tid & 15) * ST4 + (tid >> 4);             // T2: + k*16*ST4

    // ---- 6 entangler layers ----
#pragma unroll 1
    for (int l = 0; l < NL; ++l) {
        const float* cl = &cq[l * NQ];
        const float* sl = &sq[l * NQ];

        // RX wires 8-11 [M0]
        rx_gate(R, I, cl[8],  sl[8],  8);
        rx_gate(R, I, cl[9],  sl[9],  4);
        rx_gate(R, I, cl[10], sl[10], 2);
        rx_gate(R, I, cl[11], sl[11], 1);

        // T1: M0 -> M1
        __syncthreads();
#pragma unroll
        for (int k = 0; k < 16; ++k)
            sm4[st + k] = make_float4(lo32(R[k]), hi32(R[k]), lo32(I[k]), hi32(I[k]));
        __syncthreads();
#pragma unroll
        for (int k = 0; k < 16; ++k) {
            const float4 v = sm4[base1 + k * ST4];
            R[k] = pk2(v.x, v.y); I[k] = pk2(v.z, v.w);
        }

        // RX wires 4-7 [M1]
        rx_gate(R, I, cl[4], sl[4], 8);
        rx_gate(R, I, cl[5], sl[5], 4);
        rx_gate(R, I, cl[6], sl[6], 2);
        rx_gate(R, I, cl[7], sl[7], 1);

        // T2: M1 -> M2
        __syncthreads();
#pragma unroll
        for (int k = 0; k < 16; ++k)
            sm4[st + k] = make_float4(lo32(R[k]), hi32(R[k]), lo32(I[k]), hi32(I[k]));
        __syncthreads();
#pragma unroll
        for (int k = 0; k < 16; ++k) {
            const float4 v = sm4[base2 + k * (16 * ST4)];
            R[k] = pk2(v.x, v.y); I[k] = pk2(v.z, v.w);
        }

        // RX wires 0-3 [M2]
        rx_gate(R, I, cl[0], sl[0], 8);
        rx_gate(R, I, cl[1], sl[1], 4);
        rx_gate(R, I, cl[2], sl[2], 2);
        rx_gate(R, I, cl[3], sl[3], 1);

        // T3: fused CNOT-ring permutation, M2 -> M0
        __syncthreads();
#pragma unroll
        for (int k = 0; k < 16; ++k)
            sm4[st + k] = make_float4(lo32(R[k]), hi32(R[k]), lo32(I[k]), hi32(I[k]));
        __syncthreads();
#pragma unroll
        for (int k = 0; k < 16; ++k) {
            const int off = (k & 1) ? (int)(off3p[k >> 1] >> 16)
                                    : (int)(off3p[k >> 1] & 0xFFFFu);
            const float4 v = sm4[off];
            R[k] = pk2(v.x, v.y); I[k] = pk2(v.z, v.w);
        }
    }

    // ---- <Z_w> readout (M0; lanes = samples, kept separate) ----
    u64 pt = 0ull, z8 = 0ull, z9 = 0ull, z10 = 0ull, z11 = 0ull;
#pragma unroll
    for (int k = 0; k < 16; ++k) {
        const u64 P = fma2(R[k], R[k], mul2(I[k], I[k]));
        pt  = add2(pt, P);
        z8  = add2(z8,  (k & 8) ? (P ^ SGN2) : P);
        z9  = add2(z9,  (k & 4) ? (P ^ SGN2) : P);
        z10 = add2(z10, (k & 2) ? (P ^ SGN2) : P);
        z11 = add2(z11, (k & 1) ? (P ^ SGN2) : P);
    }

    u64 z12[NQ];
#pragma unroll
    for (int w = 0; w < 8; ++w)                  // wires 0..7 <- row bit (7-w)
        z12[w] = ((tid >> (7 - w)) & 1) ? (pt ^ SGN2) : pt;
    z12[8] = z8; z12[9] = z9; z12[10] = z10; z12[11] = z11;

#pragma unroll
    for (int w = 0; w < NQ; ++w) {
#pragma unroll
        for (int o = 16; o > 0; o >>= 1)
            z12[w] = add2(z12[w], __shfl_xor_sync(0xffffffffu, z12[w], o));
    }
    if (lane == 0) {
#pragma unroll
        for (int w = 0; w < NQ; ++w) redu[warp][w] = z12[w];
    }
    __syncthreads();
    if (tid < NQ) {
        u64 acc = redu[0][tid];
#pragma unroll
        for (int ww = 1; ww < 8; ++ww) acc = add2(acc, redu[ww][tid]);
        zfu[tid] = acc;
    }
    __syncthreads();

    // ---- classifier head: 2 samples x 64 classes ----
    if (tid < 2 * NC) {
        const int c = tid & (NC - 1);
        const int s = tid >> 6;
        float acc = bias[c];
#pragma unroll
        for (int w = 0; w < NQ; ++w) {
            const float zw = s ? hi32(zfu[w]) : lo32(zfu[w]);
            acc = fmaf(zw, W[c * NQ + w], acc);
        }
        out[(b0 + s) * NC + c] = acc;
    }
}

extern "C" void kernel_launch(void* const* d_in, const int* in_sizes, int n_in,
                              void* d_out, int out_size)
{
    const float* x  = (const float*)d_in[0];   // (512, 12)
    const float* qw = (const float*)d_in[1];   // (6, 12)
    const float* W  = (const float*)d_in[2];   // (64, 12)
    const float* bs = (const float*)d_in[3];   // (64,)
    float* out = (float*)d_out;                // (512, 64)

    const int smem = SMEM4 * (int)sizeof(float4);   // 69632 B
    cudaFuncSetAttribute(qnn_kernel, cudaFuncAttributeMaxDynamicSharedMemorySize, smem);
    qnn_kernel<<<256, TPB, smem>>>(x, qw, W, bs, out);
}

// round 8
// speedup vs baseline: 1.5040x; 1.5040x over previous
#include <cuda_runtime.h>
#include <stdint.h>
#include <math.h>

#define NQ   12
#define NL   6
#define NC   64
#define TPB  128
#define STU  17                    // u64 stride per row per plane (odd -> conflict-free)
#define STF  34                    // float stride per row per plane
#define PLANEU (TPB * STU)         // 2176 u64 per plane
#define SMEMU (2 * PLANEU)         // R plane + I plane

typedef unsigned long long u64;
#define SGN2 0x8000000080000000ULL

// Amp i[11:0], wire w = bit 11-w. 32 amps/thread: reg p = k>>1, pair-lane = k&1.
// L0: k = i[4:0] (wires 7-11), tid = i[11:5].
// L1: k = i[9:5] (wires 2-6),  tid = (i[4:0]<<2) | i[11:10]  -> bits 11,10 are lane bits 1,0.
// X1: L0->L1 (swizzled store cols). X2 = CNOT-ring perm composed with L1->L0.

extern __shared__ u64 dynsm[];     // [2][PLANEU]

__device__ __forceinline__ u64 bc2(float c){ u64 r; asm("mov.b64 %0, {%1, %1};" : "=l"(r) : "f"(c)); return r; }
__device__ __forceinline__ u64 pk2(float lo, float hi){ u64 r; asm("mov.b64 %0, {%1, %2};" : "=l"(r) : "f"(lo), "f"(hi)); return r; }
__device__ __forceinline__ float lo32(u64 v){ float f; asm("{ .reg .f32 h; mov.b64 {%0, h}, %1; }" : "=f"(f) : "l"(v)); return f; }
__device__ __forceinline__ float hi32(u64 v){ float f; asm("{ .reg .f32 l; mov.b64 {l, %0}, %1; }" : "=f"(f) : "l"(v)); return f; }
__device__ __forceinline__ u64 mul2(u64 a, u64 b){ u64 r; asm("mul.rn.f32x2 %0, %1, %2;" : "=l"(r) : "l"(a), "l"(b)); return r; }
__device__ __forceinline__ u64 fma2(u64 a, u64 b, u64 c){ u64 r; asm("fma.rn.f32x2 %0, %1, %2, %3;" : "=l"(r) : "l"(a), "l"(b), "l"(c)); return r; }
__device__ __forceinline__ u64 add2(u64 a, u64 b){ u64 r; asm("add.rn.f32x2 %0, %1, %2;" : "=l"(r) : "l"(a), "l"(b)); return r; }
__device__ __forceinline__ u64 rxh(u64 C2, u64 S2, u64 T, u64 U){ return fma2(C2, T, mul2(S2, U)); }

// RX on a cross-register wire (packed mask mp) over 16-reg planes
__device__ __forceinline__ void rx_gate(u64* R, u64* I, float c, float s, int mp)
{
    const u64 C2 = bc2(c), S2 = bc2(s), N2 = S2 ^ SGN2;
#pragma unroll
    for (int p0 = 0; p0 < 16; ++p0) {
        if (p0 & mp) continue;
        const int p1 = p0 | mp;
        const u64 r0 = R[p0], i0 = I[p0], r1 = R[p1], i1 = I[p1];
        R[p0] = rxh(C2, S2, r0, i1);
        I[p0] = rxh(C2, N2, i0, r1);
        R[p1] = rxh(C2, S2, r1, i0);
        I[p1] = rxh(C2, N2, i1, r0);
    }
}

// RX on the in-register pair-lane wire (scalar lanes)
__device__ __forceinline__ void rx_lane(u64* R, u64* I, float c, float s)
{
#pragma unroll
    for (int p = 0; p < 16; ++p) {
        const float rx = lo32(R[p]), ry = hi32(R[p]);
        const float ix = lo32(I[p]), iy = hi32(I[p]);
        R[p] = pk2(fmaf(c, rx,  s * iy), fmaf(c, ry,  s * ix));
        I[p] = pk2(fmaf(c, ix, -s * ry), fmaf(c, iy, -s * rx));
    }
}

// RX on a lane-bit wire via warp shuffle (lane mask lm); RX update is role-symmetric
__device__ __forceinline__ void rx_shfl(u64* R, u64* I, float c, float s, int lm)
{
    const u64 C2 = bc2(c), S2 = bc2(s), N2 = S2 ^ SGN2;
#pragma unroll
    for (int p = 0; p < 16; ++p) {
        const u64 Rp = __shfl_xor_sync(0xffffffffu, R[p], lm);
        const u64 Ip = __shfl_xor_sync(0xffffffffu, I[p], lm);
        R[p] = rxh(C2, S2, R[p], Ip);
        I[p] = rxh(C2, N2, I[p], Rp);
    }
}

__global__ __launch_bounds__(TPB, 4)
void qnn_kernel(const float* __restrict__ x,
                const float* __restrict__ qw,
                const float* __restrict__ W,
                const float* __restrict__ bias,
                float* __restrict__ out)
{
    __shared__ float cx[NQ], sx[NQ];
    __shared__ float cq[NL * NQ], sq[NL * NQ];
    __shared__ float red[4][NQ];
    __shared__ float zf[NQ];

    u64*   const bRu = dynsm;
    u64*   const bIu = dynsm + PLANEU;
    float* const bRf = (float*)bRu;
    float* const bIf = (float*)bIu;

    const int tid  = threadIdx.x;
    const int bsmp = blockIdx.x;
    const int lane = tid & 31;
    const int warp = tid >> 5;

    if (tid < NQ) {
        float s, c;
        sincosf(0.5f * x[bsmp * NQ + tid], &s, &c);
        cx[tid] = c; sx[tid] = s;
    }
    if (tid >= 32 && tid < 32 + NL * NQ) {
        const int idx = tid - 32;
        float s, c;
        sincosf(0.5f * qw[idx], &s, &c);
        cq[idx] = c; sq[idx] = s;
    }
    __syncthreads();

    // ---- init (L0): fused AngleEmbedding product state + X2 gather offsets ----
    u64 R[16], I[16];
    uint32_t off3p[16];                // 32 X2 offsets (2x u16)
    const int base = tid << 5;

#pragma unroll
    for (int k = 0; k < 32; ++k) {
        const int i = base | k;
        float mag = 1.0f;
#pragma unroll
        for (int w = 0; w < NQ; ++w)
            mag *= ((i >> (11 - w)) & 1) ? sx[w] : cx[w];
        const int pc = __popc(i) & 3;  // amp = mag * (-i)^popcount
        float re = 0.f, im = 0.f;
        if      (pc == 0) re =  mag;
        else if (pc == 1) im = -mag;
        else if (pc == 2) re = -mag;
        else              im =  mag;

        if (k & 1) { R[k >> 1] = pk2(lo32(R[k >> 1]), re); I[k >> 1] = pk2(lo32(I[k >> 1]), im); }
        else       { R[k >> 1] = pk2(re, 0.f);             I[k >> 1] = pk2(im, 0.f); }

        // sigma(i): CNOT-ring gather source j (new[i] = old[j]); address under L1 store
        int j = i;
#pragma unroll
        for (int w = NQ - 1; w >= 0; --w) {
            const int t  = (w + 1) % NQ;
            const int bc = (j >> (11 - w)) & 1;
            j ^= bc << (11 - t);
        }
        const uint32_t row1 = (uint32_t)(((j & 31) << 2) | ((j >> 10) & 3));   // L1 tid of j
        const uint32_t off  = row1 * STF + ((j >> 5) & 31);                    // float index
        if (k & 1) off3p[k >> 1] |= off << 16;
        else       off3p[k >> 1]  = off;
    }

    const int xsw   = (tid >> 5) << 2;                                  // X1 store col swizzle (u64)
    const int stbase = tid * STU;                                       // own-row u64 store base
    // X1 load: float addr = x1b + (2q+lam)*STF
    const int x1b = ((tid & 3) << 5) * STF + ((tid >> 2) ^ ((tid & 3) << 3));

    // ---- 6 entangler layers ----
#pragma unroll 1
    for (int l = 0; l < NL; ++l) {
        const float* cl = &cq[l * NQ];
        const float* sl = &sq[l * NQ];

        // L0 gates: wires 7-10 cross, wire 11 pair-lane
        rx_gate(R, I, cl[7],  sl[7],  8);
        rx_gate(R, I, cl[8],  sl[8],  4);
        rx_gate(R, I, cl[9],  sl[9],  2);
        rx_gate(R, I, cl[10], sl[10], 1);
        rx_lane(R, I, cl[11], sl[11]);

        // X1: L0 -> L1 (swizzled store, cross-warp gather)
        __syncthreads();
#pragma unroll
        for (int p = 0; p < 16; ++p) {
            const int a = stbase + (p ^ xsw);
            bRu[a] = R[p]; bIu[a] = I[p];
        }
        __syncthreads();
#pragma unroll
        for (int q = 0; q < 16; ++q) {
            const int a0 = x1b + (2 * q) * STF, a1 = a0 + STF;
            R[q] = pk2(bRf[a0], bRf[a1]);
            I[q] = pk2(bIf[a0], bIf[a1]);
        }

        // L1 gates: wires 2-5 cross, wire 6 pair-lane, wires 0-1 lane-shuffle
        rx_gate(R, I, cl[2], sl[2], 8);
        rx_gate(R, I, cl[3], sl[3], 4);
        rx_gate(R, I, cl[4], sl[4], 2);
        rx_gate(R, I, cl[5], sl[5], 1);
        rx_lane(R, I, cl[6], sl[6]);
        rx_shfl(R, I, cl[0], sl[0], 2);     // wire 0 = bit11 = lane bit 1
        rx_shfl(R, I, cl[1], sl[1], 1);     // wire 1 = bit10 = lane bit 0

        // X2: fused CNOT-ring permutation, L1 -> L0
        __syncthreads();
#pragma unroll
        for (int p = 0; p < 16; ++p) {
            const int a = stbase + p;
            bRu[a] = R[p]; bIu[a] = I[p];
        }
        __syncthreads();
#pragma unroll
        for (int q = 0; q < 16; ++q) {
            const int o0 = off3p[q] & 0xFFFF;
            const int o1 = off3p[q] >> 16;
            R[q] = pk2(bRf[o0], bRf[o1]);
            I[q] = pk2(bIf[o0], bIf[o1]);
        }
    }

    // ---- <Z_w> readout (L0) ----
    u64 pt2 = 0ull, z7 = 0ull, z8 = 0ull, z9 = 0ull, z10 = 0ull;
    float z11 = 0.f;
#pragma unroll
    for (int p = 0; p < 16; ++p) {
        const u64 P = fma2(R[p], R[p], mul2(I[p], I[p]));
        pt2 = add2(pt2, P);
        z7  = add2(z7,  (p & 8) ? (P ^ SGN2) : P);
        z8  = add2(z8,  (p & 4) ? (P ^ SGN2) : P);
        z9  = add2(z9,  (p & 2) ? (P ^ SGN2) : P);
        z10 = add2(z10, (p & 1) ? (P ^ SGN2) : P);
        z11 += lo32(P) - hi32(P);
    }
    const float ptot = lo32(pt2) + hi32(pt2);

    float z12[NQ];
#pragma unroll
    for (int w = 0; w < 7; ++w)                  // wires 0..6 <- tid bits 6..0
        z12[w] = ((tid >> (6 - w)) & 1) ? -ptot : ptot;
    z12[7]  = lo32(z7)  + hi32(z7);
    z12[8]  = lo32(z8)  + hi32(z8);
    z12[9]  = lo32(z9)  + hi32(z9);
    z12[10] = lo32(z10) + hi32(z10);
    z12[11] = z11;

#pragma unroll
    for (int w = 0; w < NQ; ++w) {
#pragma unroll
        for (int o = 16; o > 0; o >>= 1)
            z12[w] += __shfl_xor_sync(0xffffffffu, z12[w], o);
    }
    if (lane == 0) {
#pragma unroll
        for (int w = 0; w < NQ; ++w) red[warp][w] = z12[w];
    }
    __syncthreads();
    if (tid < NQ)
        zf[tid] = red[0][tid] + red[1][tid] + red[2][tid] + red[3][tid];
    __syncthreads();

    // ---- classifier head ----
    if (tid < NC) {
        float acc = bias[tid];
#pragma unroll
        for (int w = 0; w < NQ; ++w)
            acc = fmaf(zf[w], W[tid * NQ + w], acc);
        out[bsmp * NC + tid] = acc;
    }
}

extern "C" void kernel_launch(void* const* d_in, const int* in_sizes, int n_in,
                              void* d_out, int out_size)
{
    const float* x  = (const float*)d_in[0];   // (512, 12)
    const float* qw = (const float*)d_in[1];   // (6, 12)
    const float* W  = (const float*)d_in[2];   // (64, 12)
    const float* bs = (const float*)d_in[3];   // (64,)
    float* out = (float*)d_out;                // (512, 64)

    const int smem = SMEMU * (int)sizeof(u64);   // 34816 B
    cudaFuncSetAttribute(qnn_kernel, cudaFuncAttributeMaxDynamicSharedMemorySize, smem);
    qnn_kernel<<<512, TPB, smem>>>(x, qw, W, bs, out);
}

// round 9
// speedup vs baseline: 1.5174x; 1.0089x over previous
#include <cuda_runtime.h>
#include <stdint.h>
#include <math.h>

#define NQ   12
#define NL   6
#define NC   64
#define TPB  128
#define STU  17                    // u64 stride per row per plane (odd -> conflict-free)
#define STF  34                    // float stride per row per plane
#define PLANEU (TPB * STU)         // 2176 u64 per plane
#define SMEMU (2 * PLANEU)         // R plane + I plane

typedef unsigned long long u64;
#define SGN2 0x8000000080000000ULL

// Amp i[11:0], wire w = bit 11-w. 32 amps/thread: reg p = k>>1, pair-lane = k&1.
// L0: k = i[4:0] (wires 7-11), tid = i[11:5].
// L1: k = i[9:5] (wires 2-6),  tid = (i[4:0]<<2) | i[11:10]  -> bits 11,10 are lane bits 1,0.
// X1: L0->L1 (swizzled store cols). X2 = CNOT-ring perm composed with L1->L0.

extern __shared__ u64 dynsm[];     // [2][PLANEU]

__device__ __forceinline__ u64 bc2(float c){ u64 r; asm("mov.b64 %0, {%1, %1};" : "=l"(r) : "f"(c)); return r; }
__device__ __forceinline__ u64 pk2(float lo, float hi){ u64 r; asm("mov.b64 %0, {%1, %2};" : "=l"(r) : "f"(lo), "f"(hi)); return r; }
__device__ __forceinline__ float lo32(u64 v){ float f; asm("{ .reg .f32 h; mov.b64 {%0, h}, %1; }" : "=f"(f) : "l"(v)); return f; }
__device__ __forceinline__ float hi32(u64 v){ float f; asm("{ .reg .f32 l; mov.b64 {l, %0}, %1; }" : "=f"(f) : "l"(v)); return f; }
__device__ __forceinline__ u64 mul2(u64 a, u64 b){ u64 r; asm("mul.rn.f32x2 %0, %1, %2;" : "=l"(r) : "l"(a), "l"(b)); return r; }
__device__ __forceinline__ u64 fma2(u64 a, u64 b, u64 c){ u64 r; asm("fma.rn.f32x2 %0, %1, %2, %3;" : "=l"(r) : "l"(a), "l"(b), "l"(c)); return r; }
__device__ __forceinline__ u64 add2(u64 a, u64 b){ u64 r; asm("add.rn.f32x2 %0, %1, %2;" : "=l"(r) : "l"(a), "l"(b)); return r; }
__device__ __forceinline__ u64 rxh(u64 C2, u64 S2, u64 T, u64 U){ return fma2(C2, T, mul2(S2, U)); }

// RX on a cross-register wire (packed mask mp) over 16-reg planes
__device__ __forceinline__ void rx_gate(u64* R, u64* I, float c, float s, int mp)
{
    const u64 C2 = bc2(c), S2 = bc2(s), N2 = S2 ^ SGN2;
#pragma unroll
    for (int p0 = 0; p0 < 16; ++p0) {
        if (p0 & mp) continue;
        const int p1 = p0 | mp;
        const u64 r0 = R[p0], i0 = I[p0], r1 = R[p1], i1 = I[p1];
        R[p0] = rxh(C2, S2, r0, i1);
        I[p0] = rxh(C2, N2, i0, r1);
        R[p1] = rxh(C2, S2, r1, i0);
        I[p1] = rxh(C2, N2, i1, r0);
    }
}

// RX on the in-register pair-lane wire (scalar lanes)
__device__ __forceinline__ void rx_lane(u64* R, u64* I, float c, float s)
{
#pragma unroll
    for (int p = 0; p < 16; ++p) {
        const float rx = lo32(R[p]), ry = hi32(R[p]);
        const float ix = lo32(I[p]), iy = hi32(I[p]);
        R[p] = pk2(fmaf(c, rx,  s * iy), fmaf(c, ry,  s * ix));
        I[p] = pk2(fmaf(c, ix, -s * ry), fmaf(c, iy, -s * rx));
    }
}

// RX on a lane-bit wire via warp shuffle (lane mask lm); RX update is role-symmetric
__device__ __forceinline__ void rx_shfl(u64* R, u64* I, float c, float s, int lm)
{
    const u64 C2 = bc2(c), S2 = bc2(s), N2 = S2 ^ SGN2;
#pragma unroll
    for (int p = 0; p < 16; ++p) {
        const u64 Rp = __shfl_xor_sync(0xffffffffu, R[p], lm);
        const u64 Ip = __shfl_xor_sync(0xffffffffu, I[p], lm);
        R[p] = rxh(C2, S2, R[p], Ip);
        I[p] = rxh(C2, N2, I[p], Rp);
    }
}

__global__ __launch_bounds__(TPB, 4)
void qnn_kernel(const float* __restrict__ x,
                const float* __restrict__ qw,
                const float* __restrict__ W,
                const float* __restrict__ bias,
                float* __restrict__ out)
{
    __shared__ float cx[NQ], sx[NQ];
    __shared__ float cq[NL * NQ], sq[NL * NQ];
    __shared__ float red[4][NQ];
    __shared__ float zf[NQ];

    u64*   const bRu = dynsm;
    u64*   const bIu = dynsm + PLANEU;
    float* const bRf = (float*)bRu;
    float* const bIf = (float*)bIu;

    const int tid  = threadIdx.x;
    const int bsmp = blockIdx.x;
    const int lane = tid & 31;
    const int warp = tid >> 5;

    if (tid < NQ) {
        float s, c;
        sincosf(0.5f * x[bsmp * NQ + tid], &s, &c);
        cx[tid] = c; sx[tid] = s;
    }
    if (tid >= 32 && tid < 32 + NL * NQ) {
        const int idx = tid - 32;
        float s, c;
        sincosf(0.5f * qw[idx], &s, &c);
        cq[idx] = c; sq[idx] = s;
    }
    __syncthreads();

    // ---- init (L0): fused AngleEmbedding product state + X2 gather offsets ----
    u64 R[16], I[16];
    uint32_t off3p[16];                // 32 X2 offsets (2x u16)
    const int base = tid << 5;

#pragma unroll
    for (int k = 0; k < 32; ++k) {
        const int i = base | k;
        float mag = 1.0f;
#pragma unroll
        for (int w = 0; w < NQ; ++w)
            mag *= ((i >> (11 - w)) & 1) ? sx[w] : cx[w];
        const int pc = __popc(i) & 3;  // amp = mag * (-i)^popcount
        float re = 0.f, im = 0.f;
        if      (pc == 0) re =  mag;
        else if (pc == 1) im = -mag;
        else if (pc == 2) re = -mag;
        else              im =  mag;

        if (k & 1) { R[k >> 1] = pk2(lo32(R[k >> 1]), re); I[k >> 1] = pk2(lo32(I[k >> 1]), im); }
        else       { R[k >> 1] = pk2(re, 0.f);             I[k >> 1] = pk2(im, 0.f); }

        // sigma(i): CNOT-ring gather source j (new[i] = old[j]); address under L1 store
        int j = i;
#pragma unroll
        for (int w = NQ - 1; w >= 0; --w) {
            const int t  = (w + 1) % NQ;
            const int bc = (j >> (11 - w)) & 1;
            j ^= bc << (11 - t);
        }
        const uint32_t row1 = (uint32_t)(((j & 31) << 2) | ((j >> 10) & 3));   // L1 tid of j
        const uint32_t off  = row1 * STF + ((j >> 5) & 31);                    // float index
        if (k & 1) off3p[k >> 1] |= off << 16;
        else       off3p[k >> 1]  = off;
    }

    const int xsw   = (tid >> 5) << 2;                                  // X1 store col swizzle (u64)
    const int stbase = tid * STU;                                       // own-row u64 store base
    // X1 load: float addr = x1b + (2q+lam)*STF
    const int x1b = ((tid & 3) << 5) * STF + ((tid >> 2) ^ ((tid & 3) << 3));

    // ---- 6 entangler layers ----
#pragma unroll 1
    for (int l = 0; l < NL; ++l) {
        const float* cl = &cq[l * NQ];
        const float* sl = &sq[l * NQ];

        // L0 gates: wires 7-10 cross, wire 11 pair-lane
        rx_gate(R, I, cl[7],  sl[7],  8);
        rx_gate(R, I, cl[8],  sl[8],  4);
        rx_gate(R, I, cl[9],  sl[9],  2);
        rx_gate(R, I, cl[10], sl[10], 1);
        rx_lane(R, I, cl[11], sl[11]);

        // X1: L0 -> L1 (swizzled store, cross-warp gather)
        __syncthreads();
#pragma unroll
        for (int p = 0; p < 16; ++p) {
            const int a = stbase + (p ^ xsw);
            bRu[a] = R[p]; bIu[a] = I[p];
        }
        __syncthreads();
#pragma unroll
        for (int q = 0; q < 16; ++q) {
            const int a0 = x1b + (2 * q) * STF, a1 = a0 + STF;
            R[q] = pk2(bRf[a0], bRf[a1]);
            I[q] = pk2(bIf[a0], bIf[a1]);
        }

        // L1 gates: wires 2-5 cross, wire 6 pair-lane, wires 0-1 lane-shuffle
        rx_gate(R, I, cl[2], sl[2], 8);
        rx_gate(R, I, cl[3], sl[3], 4);
        rx_gate(R, I, cl[4], sl[4], 2);
        rx_gate(R, I, cl[5], sl[5], 1);
        rx_lane(R, I, cl[6], sl[6]);
        rx_shfl(R, I, cl[0], sl[0], 2);     // wire 0 = bit11 = lane bit 1
        rx_shfl(R, I, cl[1], sl[1], 1);     // wire 1 = bit10 = lane bit 0

        // X2: fused CNOT-ring permutation, L1 -> L0
        __syncthreads();
#pragma unroll
        for (int p = 0; p < 16; ++p) {
            const int a = stbase + p;
            bRu[a] = R[p]; bIu[a] = I[p];
        }
        __syncthreads();
#pragma unroll
        for (int q = 0; q < 16; ++q) {
            const int o0 = off3p[q] & 0xFFFF;
            const int o1 = off3p[q] >> 16;
            R[q] = pk2(bRf[o0], bRf[o1]);
            I[q] = pk2(bIf[o0], bIf[o1]);
        }
    }

    // ---- <Z_w> readout (L0) ----
    u64 pt2 = 0ull, z7 = 0ull, z8 = 0ull, z9 = 0ull, z10 = 0ull;
    float z11 = 0.f;
#pragma unroll
    for (int p = 0; p < 16; ++p) {
        const u64 P = fma2(R[p], R[p], mul2(I[p], I[p]));
        pt2 = add2(pt2, P);
        z7  = add2(z7,  (p & 8) ? (P ^ SGN2) : P);
        z8  = add2(z8,  (p & 4) ? (P ^ SGN2) : P);
        z9  = add2(z9,  (p & 2) ? (P ^ SGN2) : P);
        z10 = add2(z10, (p & 1) ? (P ^ SGN2) : P);
        z11 += lo32(P) - hi32(P);
    }
    const float ptot = lo32(pt2) + hi32(pt2);

    float z12[NQ];
#pragma unroll
    for (int w = 0; w < 7; ++w)                  // wires 0..6 <- tid bits 6..0
        z12[w] = ((tid >> (6 - w)) & 1) ? -ptot : ptot;
    z12[7]  = lo32(z7)  + hi32(z7);
    z12[8]  = lo32(z8)  + hi32(z8);
    z12[9]  = lo32(z9)  + hi32(z9);
    z12[10] = lo32(z10) + hi32(z10);
    z12[11] = z11;

#pragma unroll
    for (int w = 0; w < NQ; ++w) {
#pragma unroll
        for (int o = 16; o > 0; o >>= 1)
            z12[w] += __shfl_xor_sync(0xffffffffu, z12[w], o);
    }
    if (lane == 0) {
#pragma unroll
        for (int w = 0; w < NQ; ++w) red[warp][w] = z12[w];
    }
    __syncthreads();
    if (tid < NQ)
        zf[tid] = red[0][tid] + red[1][tid] + red[2][tid] + red[3][tid];
    __syncthreads();

    // ---- classifier head ----
    if (tid < NC) {
        float acc = bias[tid];
#pragma unroll
        for (int w = 0; w < NQ; ++w)
            acc = fmaf(zf[w], W[tid * NQ + w], acc);
        out[bsmp * NC + tid] = acc;
    }
}

extern "C" void kernel_launch(void* const* d_in, const int* in_sizes, int n_in,
                              void* d_out, int out_size)
{
    const float* x  = (const float*)d_in[0];   // (512, 12)
    const float* qw = (const float*)d_in[1];   // (6, 12)
    const float* W  = (const float*)d_in[2];   // (64, 12)
    const float* bs = (const float*)d_in[3];   // (64,)
    float* out = (float*)d_out;                // (512, 64)

    const int smem = SMEMU * (int)sizeof(u64);   // 34816 B
    cudaFuncSetAttribute(qnn_kernel, cudaFuncAttributeMaxDynamicSharedMemorySize, smem);
    qnn_kernel<<<512, TPB, smem>>>(x, qw, W, bs, out);
}